// round 3
// baseline (speedup 1.0000x reference)
#include <cuda_runtime.h>
#include <cuda_fp16.h>

// Problem constants (fixed for this dataset instance)
#define BATCH       256
#define IN_FEAT     20000
#define OUT_FEAT    5000
#define NUM_EDGES   1000000

#define SPMM_CTAS   296     // 2 per SM on 148 SMs -> guaranteed single wave

// ---------------- scratch (no allocation allowed -> __device__ globals) ----
__device__ __half g_xt[IN_FEAT * BATCH];       // x transposed fp16: [IN_FEAT][BATCH], 10.24 MB
__device__ int2   g_edge[NUM_EDGES];           // dst-sorted edges: {src, w_as_int}, 8 MB
__device__ int    g_cnt[OUT_FEAT];             // edges per output column
__device__ int    g_start[OUT_FEAT];           // CSR row starts
__device__ int    g_cursor[OUT_FEAT];          // scatter cursors

// ---------------- 1) transpose x [B][IN] -> xT fp16 [IN][B]; fold cnt zeroing
__global__ void transpose_kernel(const float* __restrict__ x) {
    // fold histogram zeroing into this launch (runs before hist in stream order)
    if (blockIdx.y == 0 && blockIdx.x < 5) {
        int i = blockIdx.x * 1024 + threadIdx.y * 32 + threadIdx.x;
        if (i < OUT_FEAT) g_cnt[i] = 0;
    }
    __shared__ float tile[32][33];
    int s0 = blockIdx.x * 32;
    int b0 = blockIdx.y * 32;
    int tx = threadIdx.x;    // 0..31
    int ty = threadIdx.y;    // 0..31
    tile[ty][tx] = x[(b0 + ty) * IN_FEAT + (s0 + tx)];    // coalesced read
    __syncthreads();
    g_xt[(s0 + ty) * BATCH + (b0 + tx)] = __float2half_rn(tile[tx][ty]);
}

// ---------------- 2) histogram of dst (smem-privatized, int4 loads) ----------
__global__ void hist_kernel(const int* __restrict__ dst, int n) {
    __shared__ int h[OUT_FEAT];
    for (int i = threadIdx.x; i < OUT_FEAT; i += blockDim.x) h[i] = 0;
    __syncthreads();
    int n4 = n >> 2;
    const int4* dst4 = (const int4*)dst;
    for (int e = blockIdx.x * blockDim.x + threadIdx.x; e < n4;
         e += gridDim.x * blockDim.x) {
        int4 d = dst4[e];
        atomicAdd(&h[d.x], 1);
        atomicAdd(&h[d.y], 1);
        atomicAdd(&h[d.z], 1);
        atomicAdd(&h[d.w], 1);
    }
    // scalar tail
    if (blockIdx.x == 0) {
        for (int e = n4 * 4 + threadIdx.x; e < n; e += blockDim.x)
            atomicAdd(&h[dst[e]], 1);
    }
    __syncthreads();
    for (int i = threadIdx.x; i < OUT_FEAT; i += blockDim.x) {
        int v = h[i];
        if (v) atomicAdd(&g_cnt[i], v);
    }
}

// ---------------- 3) exclusive scan over 5000 counts (shuffle-based) ---------
#define SCAN_THREADS 1024
#define SCAN_NPT     5   // 1024*5 = 5120 >= 5000
__global__ void scan_kernel() {
    __shared__ int wsum[32];
    int t = threadIdx.x;
    int lane = t & 31, w = t >> 5;
    int local[SCAN_NPT];
    int sum = 0;
#pragma unroll
    for (int k = 0; k < SCAN_NPT; k++) {
        int idx = t * SCAN_NPT + k;
        int v = (idx < OUT_FEAT) ? g_cnt[idx] : 0;
        local[k] = v;
        sum += v;
    }
    // inclusive scan of per-thread sums within warp
    int s = sum;
#pragma unroll
    for (int off = 1; off < 32; off <<= 1) {
        int u = __shfl_up_sync(0xFFFFFFFFu, s, off);
        if (lane >= off) s += u;
    }
    if (lane == 31) wsum[w] = s;
    __syncthreads();
    if (w == 0) {
        int v = wsum[lane];
        int sv = v;
#pragma unroll
        for (int off = 1; off < 32; off <<= 1) {
            int u = __shfl_up_sync(0xFFFFFFFFu, sv, off);
            if (lane >= off) sv += u;
        }
        wsum[lane] = sv;   // inclusive warp totals
    }
    __syncthreads();
    int run = (w > 0 ? wsum[w - 1] : 0) + (s - sum);  // exclusive prefix
#pragma unroll
    for (int k = 0; k < SCAN_NPT; k++) {
        int idx = t * SCAN_NPT + k;
        if (idx < OUT_FEAT) {
            g_start[idx]  = run;
            g_cursor[idx] = run;
            run += local[k];
        }
    }
}

// ---------------- 4) scatter edges into CSR buckets (vectorized) -------------
__global__ void scatter_kernel(const int* __restrict__ src,
                               const int* __restrict__ dst,
                               const float* __restrict__ w, int n) {
    int n4 = n >> 2;
    int e = blockIdx.x * blockDim.x + threadIdx.x;
    if (e < n4) {
        int4   s4 = ((const int4*)src)[e];
        int4   d4 = ((const int4*)dst)[e];
        float4 w4 = ((const float4*)w)[e];
        int p;
        p = atomicAdd(&g_cursor[d4.x], 1); g_edge[p] = make_int2(s4.x, __float_as_int(w4.x));
        p = atomicAdd(&g_cursor[d4.y], 1); g_edge[p] = make_int2(s4.y, __float_as_int(w4.y));
        p = atomicAdd(&g_cursor[d4.z], 1); g_edge[p] = make_int2(s4.z, __float_as_int(w4.z));
        p = atomicAdd(&g_cursor[d4.w], 1); g_edge[p] = make_int2(s4.w, __float_as_int(w4.w));
    }
    // scalar tail
    if (blockIdx.x == 0 && threadIdx.x < (n & 3)) {
        int i = n4 * 4 + threadIdx.x;
        int pos = atomicAdd(&g_cursor[dst[i]], 1);
        g_edge[pos] = make_int2(src[i], __float_as_int(w[i]));
    }
}

// ---------------- 5) main SpMM: one column per CTA, 8 warps split edges ------
// Lane t of each warp accumulates batch elements [8t, 8t+7] (one uint4 = 8 halves
// of the fp16 xT row). 8 warps each take a contiguous 1/8 chunk of the column's
// edge list; partial accumulators reduced through smem.
__device__ __forceinline__ void accum8(float acc[8], uint4 v, float wv) {
    float2 f;
    f = __half22float2(*reinterpret_cast<__half2*>(&v.x)); acc[0] += wv * f.x; acc[1] += wv * f.y;
    f = __half22float2(*reinterpret_cast<__half2*>(&v.y)); acc[2] += wv * f.x; acc[3] += wv * f.y;
    f = __half22float2(*reinterpret_cast<__half2*>(&v.z)); acc[4] += wv * f.x; acc[5] += wv * f.y;
    f = __half22float2(*reinterpret_cast<__half2*>(&v.w)); acc[6] += wv * f.x; acc[7] += wv * f.y;
}

__global__ __launch_bounds__(256) void spmm_kernel(const float* __restrict__ bias,
                                                   float* __restrict__ out) {
    __shared__ float sAcc[8][BATCH];     // 8 warps x 256 batch partials
    int warp = threadIdx.x >> 5;
    int t    = threadIdx.x & 31;
    const uint4* __restrict__ xt = (const uint4*)g_xt;   // 32 uint4 per xT row

    for (int col = blockIdx.x; col < OUT_FEAT; col += SPMM_CTAS) {
        int beg = g_start[col];
        int n   = g_cnt[col];
        int ch  = (n + 7) >> 3;                 // edges per warp
        int lo  = warp * ch;
        int hi  = min(lo + ch, n);
        const int2* __restrict__ ep = g_edge + beg;

        float acc[8] = {0.f, 0.f, 0.f, 0.f, 0.f, 0.f, 0.f, 0.f};

        int j = lo;
        for (; j + 4 <= hi; j += 4) {
            int2 e0 = __ldg(ep + j + 0);
            int2 e1 = __ldg(ep + j + 1);
            int2 e2 = __ldg(ep + j + 2);
            int2 e3 = __ldg(ep + j + 3);
            uint4 v0 = __ldg(xt + (size_t)e0.x * 32 + t);
            uint4 v1 = __ldg(xt + (size_t)e1.x * 32 + t);
            uint4 v2 = __ldg(xt + (size_t)e2.x * 32 + t);
            uint4 v3 = __ldg(xt + (size_t)e3.x * 32 + t);
            accum8(acc, v0, __int_as_float(e0.y));
            accum8(acc, v1, __int_as_float(e1.y));
            accum8(acc, v2, __int_as_float(e2.y));
            accum8(acc, v3, __int_as_float(e3.y));
        }
        for (; j < hi; j++) {
            int2 e = __ldg(ep + j);
            uint4 v = __ldg(xt + (size_t)e.x * 32 + t);
            accum8(acc, v, __int_as_float(e.y));
        }

#pragma unroll
        for (int i = 0; i < 8; i++) sAcc[warp][t * 8 + i] = acc[i];
        __syncthreads();

        // reduce 8 partials; thread b handles batch element b
        int b = threadIdx.x;
        float s = sAcc[0][b] + sAcc[1][b] + sAcc[2][b] + sAcc[3][b]
                + sAcc[4][b] + sAcc[5][b] + sAcc[6][b] + sAcc[7][b];
        float r = tanhf(s + __ldg(bias + col));
        out[(size_t)b * OUT_FEAT + col] = r;
        __syncthreads();   // protect sAcc before next column overwrites it
    }
}

// ---------------- launch ------------------------------------------------------
extern "C" void kernel_launch(void* const* d_in, const int* in_sizes, int n_in,
                              void* d_out, int out_size) {
    const float* x    = (const float*)d_in[0];
    const int*   src  = (const int*)  d_in[1];
    const int*   dst  = (const int*)  d_in[2];
    const float* w    = (const float*)d_in[3];
    const float* bias = (const float*)d_in[4];
    float* out = (float*)d_out;

    int E = in_sizes[1];   // NUM_EDGES

    transpose_kernel<<<dim3(IN_FEAT / 32, BATCH / 32), dim3(32, 32)>>>(x);
    hist_kernel<<<128, 1024>>>(dst, E);
    scan_kernel<<<1, SCAN_THREADS>>>();
    scatter_kernel<<<(E / 4 + 255) / 256, 256>>>(src, dst, w, E);
    spmm_kernel<<<SPMM_CTAS, 256>>>(bias, out);
}

// round 4
// speedup vs baseline: 1.6661x; 1.6661x over previous
#include <cuda_runtime.h>
#include <cuda_fp16.h>

// Problem constants (fixed for this dataset instance)
#define BATCH       256
#define IN_FEAT     20000
#define OUT_FEAT    5000
#define NUM_EDGES   1000000

#define NB          256     // counting-sort blocks
#define SPMM_CTAS   592     // 4 per SM on 148 SMs -> single wave, 32 warps/SM

// ---------------- scratch (no allocation allowed -> __device__ globals) ----
__device__ __half g_xt[IN_FEAT * BATCH];       // x transposed fp16: [IN_FEAT][BATCH], 10.24 MB
__device__ int2   g_edge[NUM_EDGES];           // dst-sorted edges: {src, w_as_int}, 8 MB
__device__ int    g_bh[NB * OUT_FEAT];         // per-block histograms / offsets, 5.12 MB
__device__ int    g_cnt[OUT_FEAT];             // edges per output column
__device__ int    g_start[OUT_FEAT];           // CSR row starts

// ---------------- 1) transpose x [B][IN] -> xT fp16 [IN][B] ------------------
__global__ void transpose_kernel(const float* __restrict__ x) {
    __shared__ float tile[32][33];
    int s0 = blockIdx.x * 32;
    int b0 = blockIdx.y * 32;
    int tx = threadIdx.x;    // 0..31
    int ty = threadIdx.y;    // 0..31
    tile[ty][tx] = x[(b0 + ty) * IN_FEAT + (s0 + tx)];    // coalesced read
    __syncthreads();
    g_xt[(s0 + ty) * BATCH + (b0 + tx)] = __float2half_rn(tile[tx][ty]);
}

// ---------------- 2a) per-block histogram (smem only; coalesced global out) --
__global__ __launch_bounds__(1024) void hist_block_kernel(const int* __restrict__ dst,
                                                          int n, int chunk) {
    __shared__ int h[OUT_FEAT];
    for (int i = threadIdx.x; i < OUT_FEAT; i += 1024) h[i] = 0;
    __syncthreads();
    int b  = blockIdx.x;
    int lo = b * chunk;
    int hi = min(lo + chunk, n);
    for (int e = lo + threadIdx.x; e < hi; e += 1024)
        atomicAdd(&h[dst[e]], 1);
    __syncthreads();
    int* out = g_bh + b * OUT_FEAT;
    for (int i = threadIdx.x; i < OUT_FEAT; i += 1024) out[i] = h[i];
}

// ---------------- 2b) per-column scan over the NB block counts ---------------
// Block handles 32 columns. Coalesced tile load (NB x 32), warp-per-column scan
// in smem, coalesced write-back of exclusive block offsets; totals -> g_cnt.
__global__ __launch_bounds__(1024) void colscan_kernel() {
    __shared__ int tile[NB][33];
    int c0 = blockIdx.x * 32;
    int tx = threadIdx.x & 31;
    int ty = threadIdx.x >> 5;

    // load: 8 passes of (32 block-rows x 32 cols)
#pragma unroll
    for (int p = 0; p < 8; p++) {
        int b = p * 32 + ty;
        int c = c0 + tx;
        tile[b][tx] = (c < OUT_FEAT) ? g_bh[b * OUT_FEAT + c] : 0;
    }
    __syncthreads();

    // warp ty owns tile column ty; lane tx owns rows [tx*8, tx*8+7]
    int vals[8];
    int lsum = 0;
#pragma unroll
    for (int k = 0; k < 8; k++) {
        vals[k] = tile[tx * 8 + k][ty];
        lsum += vals[k];
    }
    int s = lsum;
#pragma unroll
    for (int off = 1; off < 32; off <<= 1) {
        int u = __shfl_up_sync(0xFFFFFFFFu, s, off);
        if (tx >= off) s += u;
    }
    int run = s - lsum;  // exclusive prefix over earlier lanes
#pragma unroll
    for (int k = 0; k < 8; k++) {
        tile[tx * 8 + k][ty] = run;
        run += vals[k];
    }
    if (tx == 31 && (c0 + ty) < OUT_FEAT) g_cnt[c0 + ty] = run;  // column total
    __syncthreads();

    // write back exclusive offsets, same coalesced pattern
#pragma unroll
    for (int p = 0; p < 8; p++) {
        int b = p * 32 + ty;
        int c = c0 + tx;
        if (c < OUT_FEAT) g_bh[b * OUT_FEAT + c] = tile[b][tx];
    }
}

// ---------------- 3) exclusive scan over 5000 column totals ------------------
#define SCAN_THREADS 1024
#define SCAN_NPT     5   // 1024*5 = 5120 >= 5000
__global__ void scan_kernel() {
    __shared__ int wsum[32];
    int t = threadIdx.x;
    int lane = t & 31, w = t >> 5;
    int local[SCAN_NPT];
    int sum = 0;
#pragma unroll
    for (int k = 0; k < SCAN_NPT; k++) {
        int idx = t * SCAN_NPT + k;
        int v = (idx < OUT_FEAT) ? g_cnt[idx] : 0;
        local[k] = v;
        sum += v;
    }
    int s = sum;
#pragma unroll
    for (int off = 1; off < 32; off <<= 1) {
        int u = __shfl_up_sync(0xFFFFFFFFu, s, off);
        if (lane >= off) s += u;
    }
    if (lane == 31) wsum[w] = s;
    __syncthreads();
    if (w == 0) {
        int sv = wsum[lane];
#pragma unroll
        for (int off = 1; off < 32; off <<= 1) {
            int u = __shfl_up_sync(0xFFFFFFFFu, sv, off);
            if (lane >= off) sv += u;
        }
        wsum[lane] = sv;
    }
    __syncthreads();
    int run = (w > 0 ? wsum[w - 1] : 0) + (s - sum);
#pragma unroll
    for (int k = 0; k < SCAN_NPT; k++) {
        int idx = t * SCAN_NPT + k;
        if (idx < OUT_FEAT) {
            g_start[idx] = run;
            run += local[k];
        }
    }
}

// ---------------- 4) scatter with exact per-block offsets (smem atomics) -----
__global__ __launch_bounds__(1024) void scatter_block_kernel(const int* __restrict__ src,
                                                             const int* __restrict__ dst,
                                                             const float* __restrict__ w,
                                                             int n, int chunk) {
    __shared__ int cur[OUT_FEAT];
    int b = blockIdx.x;
    const int* off = g_bh + b * OUT_FEAT;
    for (int i = threadIdx.x; i < OUT_FEAT; i += 1024)
        cur[i] = g_start[i] + off[i];
    __syncthreads();
    int lo = b * chunk;
    int hi = min(lo + chunk, n);
    for (int e = lo + threadIdx.x; e < hi; e += 1024) {
        int d = dst[e];
        int p = atomicAdd(&cur[d], 1);            // smem atomic: ~30 cyc, low contention
        g_edge[p] = make_int2(src[e], __float_as_int(w[e]));
    }
}

// ---------------- 5) main SpMM: one column per CTA, 8 warps split edges ------
__device__ __forceinline__ void accum8(float acc[8], uint4 v, float wv) {
    float2 f;
    f = __half22float2(*reinterpret_cast<__half2*>(&v.x)); acc[0] += wv * f.x; acc[1] += wv * f.y;
    f = __half22float2(*reinterpret_cast<__half2*>(&v.y)); acc[2] += wv * f.x; acc[3] += wv * f.y;
    f = __half22float2(*reinterpret_cast<__half2*>(&v.z)); acc[4] += wv * f.x; acc[5] += wv * f.y;
    f = __half22float2(*reinterpret_cast<__half2*>(&v.w)); acc[6] += wv * f.x; acc[7] += wv * f.y;
}

__global__ __launch_bounds__(256) void spmm_kernel(const float* __restrict__ bias,
                                                   float* __restrict__ out) {
    __shared__ float sAcc[8][BATCH];     // 8 warps x 256 batch partials
    int warp = threadIdx.x >> 5;
    int t    = threadIdx.x & 31;
    const uint4* __restrict__ xt = (const uint4*)g_xt;   // 32 uint4 per xT row

    for (int col = blockIdx.x; col < OUT_FEAT; col += SPMM_CTAS) {
        int beg = g_start[col];
        int n   = g_cnt[col];
        int ch  = (n + 7) >> 3;
        int lo  = warp * ch;
        int hi  = min(lo + ch, n);
        const int2* __restrict__ ep = g_edge + beg;

        float acc[8] = {0.f, 0.f, 0.f, 0.f, 0.f, 0.f, 0.f, 0.f};

        int j = lo;
        for (; j + 4 <= hi; j += 4) {
            int2 e0 = __ldg(ep + j + 0);
            int2 e1 = __ldg(ep + j + 1);
            int2 e2 = __ldg(ep + j + 2);
            int2 e3 = __ldg(ep + j + 3);
            uint4 v0 = __ldg(xt + (size_t)e0.x * 32 + t);
            uint4 v1 = __ldg(xt + (size_t)e1.x * 32 + t);
            uint4 v2 = __ldg(xt + (size_t)e2.x * 32 + t);
            uint4 v3 = __ldg(xt + (size_t)e3.x * 32 + t);
            accum8(acc, v0, __int_as_float(e0.y));
            accum8(acc, v1, __int_as_float(e1.y));
            accum8(acc, v2, __int_as_float(e2.y));
            accum8(acc, v3, __int_as_float(e3.y));
        }
        for (; j < hi; j++) {
            int2 e = __ldg(ep + j);
            uint4 v = __ldg(xt + (size_t)e.x * 32 + t);
            accum8(acc, v, __int_as_float(e.y));
        }

        // two 128-bit stores instead of eight 32-bit
        float4* dstv = (float4*)&sAcc[warp][t * 8];
        dstv[0] = make_float4(acc[0], acc[1], acc[2], acc[3]);
        dstv[1] = make_float4(acc[4], acc[5], acc[6], acc[7]);
        __syncthreads();

        int b = threadIdx.x;
        float s = sAcc[0][b] + sAcc[1][b] + sAcc[2][b] + sAcc[3][b]
                + sAcc[4][b] + sAcc[5][b] + sAcc[6][b] + sAcc[7][b];
        float r = tanhf(s + __ldg(bias + col));
        out[(size_t)b * OUT_FEAT + col] = r;
        __syncthreads();   // protect sAcc before next column overwrites it
    }
}

// ---------------- launch ------------------------------------------------------
extern "C" void kernel_launch(void* const* d_in, const int* in_sizes, int n_in,
                              void* d_out, int out_size) {
    const float* x    = (const float*)d_in[0];
    const int*   src  = (const int*)  d_in[1];
    const int*   dst  = (const int*)  d_in[2];
    const float* w    = (const float*)d_in[3];
    const float* bias = (const float*)d_in[4];
    float* out = (float*)d_out;

    int E = in_sizes[1];                 // NUM_EDGES
    int chunk = (E + NB - 1) / NB;

    transpose_kernel<<<dim3(IN_FEAT / 32, BATCH / 32), dim3(32, 32)>>>(x);
    hist_block_kernel<<<NB, 1024>>>(dst, E, chunk);
    colscan_kernel<<<(OUT_FEAT + 31) / 32, 1024>>>();
    scan_kernel<<<1, SCAN_THREADS>>>();
    scatter_block_kernel<<<NB, 1024>>>(src, dst, w, E, chunk);
    spmm_kernel<<<SPMM_CTAS, 256>>>(bias, out);
}

// round 5
// speedup vs baseline: 1.6859x; 1.0119x over previous
#include <cuda_runtime.h>
#include <cuda_fp16.h>

// Problem constants (fixed for this dataset instance)
#define BATCH       256
#define IN_FEAT     20000
#define OUT_FEAT    5000
#define NUM_EDGES   1000000

#define NB          256     // counting-sort blocks
#define SPMM_CTAS   592     // 4 per SM on 148 SMs -> single wave, 32 warps/SM

// ---------------- scratch (no allocation allowed -> __device__ globals) ----
__device__ __half g_xt[IN_FEAT * BATCH];       // x transposed fp16: [IN_FEAT][BATCH], 10.24 MB
__device__ int2   g_edge[NUM_EDGES];           // dst-sorted edges: {src, w_as_int}, 8 MB
__device__ int    g_bh[NB * OUT_FEAT];         // per-block histograms / offsets, 5.12 MB
__device__ int    g_cnt[OUT_FEAT];             // edges per output column
__device__ int    g_start[OUT_FEAT];           // CSR row starts

// ---------------- 1) transpose x [B][IN] -> xT fp16 [IN][B] ------------------
__global__ void transpose_kernel(const float* __restrict__ x) {
    __shared__ float tile[32][33];
    int s0 = blockIdx.x * 32;
    int b0 = blockIdx.y * 32;
    int tx = threadIdx.x;    // 0..31
    int ty = threadIdx.y;    // 0..31
    tile[ty][tx] = x[(b0 + ty) * IN_FEAT + (s0 + tx)];    // coalesced read
    __syncthreads();
    g_xt[(s0 + ty) * BATCH + (b0 + tx)] = __float2half_rn(tile[tx][ty]);
}

// ---------------- 2a) per-block histogram (smem only; coalesced global out) --
__global__ __launch_bounds__(1024) void hist_block_kernel(const int* __restrict__ dst,
                                                          int n, int chunk) {
    __shared__ int h[OUT_FEAT];
    for (int i = threadIdx.x; i < OUT_FEAT; i += 1024) h[i] = 0;
    __syncthreads();
    int b  = blockIdx.x;
    int lo = b * chunk;
    int hi = min(lo + chunk, n);
    for (int e = lo + threadIdx.x; e < hi; e += 1024)
        atomicAdd(&h[dst[e]], 1);
    __syncthreads();
    int* out = g_bh + b * OUT_FEAT;
    for (int i = threadIdx.x; i < OUT_FEAT; i += 1024) out[i] = h[i];
}

// ---------------- 2b) per-column scan over the NB block counts ---------------
// Block handles 32 columns. Coalesced tile load (NB x 32), warp-per-column scan
// in smem, coalesced write-back of exclusive block offsets; totals -> g_cnt.
__global__ __launch_bounds__(1024) void colscan_kernel() {
    __shared__ int tile[NB][33];
    int c0 = blockIdx.x * 32;
    int tx = threadIdx.x & 31;
    int ty = threadIdx.x >> 5;

    // load: 8 passes of (32 block-rows x 32 cols)
#pragma unroll
    for (int p = 0; p < 8; p++) {
        int b = p * 32 + ty;
        int c = c0 + tx;
        tile[b][tx] = (c < OUT_FEAT) ? g_bh[b * OUT_FEAT + c] : 0;
    }
    __syncthreads();

    // warp ty owns tile column ty; lane tx owns rows [tx*8, tx*8+7]
    int vals[8];
    int lsum = 0;
#pragma unroll
    for (int k = 0; k < 8; k++) {
        vals[k] = tile[tx * 8 + k][ty];
        lsum += vals[k];
    }
    int s = lsum;
#pragma unroll
    for (int off = 1; off < 32; off <<= 1) {
        int u = __shfl_up_sync(0xFFFFFFFFu, s, off);
        if (tx >= off) s += u;
    }
    int run = s - lsum;  // exclusive prefix over earlier lanes
#pragma unroll
    for (int k = 0; k < 8; k++) {
        tile[tx * 8 + k][ty] = run;
        run += vals[k];
    }
    if (tx == 31 && (c0 + ty) < OUT_FEAT) g_cnt[c0 + ty] = run;  // column total
    __syncthreads();

    // write back exclusive offsets, same coalesced pattern
#pragma unroll
    for (int p = 0; p < 8; p++) {
        int b = p * 32 + ty;
        int c = c0 + tx;
        if (c < OUT_FEAT) g_bh[b * OUT_FEAT + c] = tile[b][tx];
    }
}

// ---------------- 3) exclusive scan over 5000 column totals ------------------
#define SCAN_THREADS 1024
#define SCAN_NPT     5   // 1024*5 = 5120 >= 5000
__global__ void scan_kernel() {
    __shared__ int wsum[32];
    int t = threadIdx.x;
    int lane = t & 31, w = t >> 5;
    int local[SCAN_NPT];
    int sum = 0;
#pragma unroll
    for (int k = 0; k < SCAN_NPT; k++) {
        int idx = t * SCAN_NPT + k;
        int v = (idx < OUT_FEAT) ? g_cnt[idx] : 0;
        local[k] = v;
        sum += v;
    }
    int s = sum;
#pragma unroll
    for (int off = 1; off < 32; off <<= 1) {
        int u = __shfl_up_sync(0xFFFFFFFFu, s, off);
        if (lane >= off) s += u;
    }
    if (lane == 31) wsum[w] = s;
    __syncthreads();
    if (w == 0) {
        int sv = wsum[lane];
#pragma unroll
        for (int off = 1; off < 32; off <<= 1) {
            int u = __shfl_up_sync(0xFFFFFFFFu, sv, off);
            if (lane >= off) sv += u;
        }
        wsum[lane] = sv;
    }
    __syncthreads();
    int run = (w > 0 ? wsum[w - 1] : 0) + (s - sum);
#pragma unroll
    for (int k = 0; k < SCAN_NPT; k++) {
        int idx = t * SCAN_NPT + k;
        if (idx < OUT_FEAT) {
            g_start[idx] = run;
            run += local[k];
        }
    }
}

// ---------------- 4) scatter with exact per-block offsets (smem atomics) -----
__global__ __launch_bounds__(1024) void scatter_block_kernel(const int* __restrict__ src,
                                                             const int* __restrict__ dst,
                                                             const float* __restrict__ w,
                                                             int n, int chunk) {
    __shared__ int cur[OUT_FEAT];
    int b = blockIdx.x;
    const int* off = g_bh + b * OUT_FEAT;
    for (int i = threadIdx.x; i < OUT_FEAT; i += 1024)
        cur[i] = g_start[i] + off[i];
    __syncthreads();
    int lo = b * chunk;
    int hi = min(lo + chunk, n);
    for (int e = lo + threadIdx.x; e < hi; e += 1024) {
        int d = dst[e];
        int p = atomicAdd(&cur[d], 1);            // smem atomic: ~30 cyc, low contention
        g_edge[p] = make_int2(src[e], __float_as_int(w[e]));
    }
}

// ---------------- 5) main SpMM: one column per CTA, 8 warps split edges ------
__device__ __forceinline__ void accum8(float acc[8], uint4 v, float wv) {
    float2 f;
    f = __half22float2(*reinterpret_cast<__half2*>(&v.x)); acc[0] += wv * f.x; acc[1] += wv * f.y;
    f = __half22float2(*reinterpret_cast<__half2*>(&v.y)); acc[2] += wv * f.x; acc[3] += wv * f.y;
    f = __half22float2(*reinterpret_cast<__half2*>(&v.z)); acc[4] += wv * f.x; acc[5] += wv * f.y;
    f = __half22float2(*reinterpret_cast<__half2*>(&v.w)); acc[6] += wv * f.x; acc[7] += wv * f.y;
}

__global__ __launch_bounds__(256) void spmm_kernel(const float* __restrict__ bias,
                                                   float* __restrict__ out) {
    __shared__ float sAcc[8][BATCH];     // 8 warps x 256 batch partials
    int warp = threadIdx.x >> 5;
    int t    = threadIdx.x & 31;
    const uint4* __restrict__ xt = (const uint4*)g_xt;   // 32 uint4 per xT row

    for (int col = blockIdx.x; col < OUT_FEAT; col += SPMM_CTAS) {
        int beg = g_start[col];
        int n   = g_cnt[col];
        int ch  = (n + 7) >> 3;
        int lo  = warp * ch;
        int hi  = min(lo + ch, n);
        const int2* __restrict__ ep = g_edge + beg;

        float acc[8] = {0.f, 0.f, 0.f, 0.f, 0.f, 0.f, 0.f, 0.f};

        int j = lo;
        for (; j + 4 <= hi; j += 4) {
            int2 e0 = __ldg(ep + j + 0);
            int2 e1 = __ldg(ep + j + 1);
            int2 e2 = __ldg(ep + j + 2);
            int2 e3 = __ldg(ep + j + 3);
            uint4 v0 = __ldg(xt + (size_t)e0.x * 32 + t);
            uint4 v1 = __ldg(xt + (size_t)e1.x * 32 + t);
            uint4 v2 = __ldg(xt + (size_t)e2.x * 32 + t);
            uint4 v3 = __ldg(xt + (size_t)e3.x * 32 + t);
            accum8(acc, v0, __int_as_float(e0.y));
            accum8(acc, v1, __int_as_float(e1.y));
            accum8(acc, v2, __int_as_float(e2.y));
            accum8(acc, v3, __int_as_float(e3.y));
        }
        for (; j < hi; j++) {
            int2 e = __ldg(ep + j);
            uint4 v = __ldg(xt + (size_t)e.x * 32 + t);
            accum8(acc, v, __int_as_float(e.y));
        }

        // two 128-bit stores instead of eight 32-bit
        float4* dstv = (float4*)&sAcc[warp][t * 8];
        dstv[0] = make_float4(acc[0], acc[1], acc[2], acc[3]);
        dstv[1] = make_float4(acc[4], acc[5], acc[6], acc[7]);
        __syncthreads();

        int b = threadIdx.x;
        float s = sAcc[0][b] + sAcc[1][b] + sAcc[2][b] + sAcc[3][b]
                + sAcc[4][b] + sAcc[5][b] + sAcc[6][b] + sAcc[7][b];
        float r = tanhf(s + __ldg(bias + col));
        out[(size_t)b * OUT_FEAT + col] = r;
        __syncthreads();   // protect sAcc before next column overwrites it
    }
}

// ---------------- launch ------------------------------------------------------
extern "C" void kernel_launch(void* const* d_in, const int* in_sizes, int n_in,
                              void* d_out, int out_size) {
    const float* x    = (const float*)d_in[0];
    const int*   src  = (const int*)  d_in[1];
    const int*   dst  = (const int*)  d_in[2];
    const float* w    = (const float*)d_in[3];
    const float* bias = (const float*)d_in[4];
    float* out = (float*)d_out;

    int E = in_sizes[1];                 // NUM_EDGES
    int chunk = (E + NB - 1) / NB;

    transpose_kernel<<<dim3(IN_FEAT / 32, BATCH / 32), dim3(32, 32)>>>(x);
    hist_block_kernel<<<NB, 1024>>>(dst, E, chunk);
    colscan_kernel<<<(OUT_FEAT + 31) / 32, 1024>>>();
    scan_kernel<<<1, SCAN_THREADS>>>();
    scatter_block_kernel<<<NB, 1024>>>(src, dst, w, E, chunk);
    spmm_kernel<<<SPMM_CTAS, 256>>>(bias, out);
}

// round 6
// speedup vs baseline: 1.9984x; 1.1854x over previous
#include <cuda_runtime.h>
#include <cuda_fp16.h>

// Problem constants (fixed for this dataset instance)
#define BATCH       256
#define IN_FEAT     20000
#define OUT_FEAT    5000
#define NUM_EDGES   1000000

#define NB          256     // counting-sort blocks
#define SPMM_CTAS   592     // 4 per SM on 148 SMs -> single wave, 32 warps/SM

// ---------------- scratch (no allocation allowed -> __device__ globals) ----
__device__ __half g_xt[IN_FEAT * BATCH];       // x transposed fp16: [IN_FEAT][BATCH], 10.24 MB
__device__ int2   g_edge[NUM_EDGES];           // dst-sorted edges: {src, w_as_int}, 8 MB
__device__ int    g_bh[NB * OUT_FEAT];         // per-block histograms / offsets, 5.12 MB
__device__ int    g_cnt[OUT_FEAT];             // edges per output column
__device__ int    g_start[OUT_FEAT];           // CSR row starts (written by scatter block 0)

// ---------------- 1) transpose x [B][IN] -> xT fp16 [IN][B] ------------------
// Block (32,32) handles a 64(b) x 32(s) tile; stores are half2 -> each warp
// writes 128 contiguous bytes.
__global__ __launch_bounds__(1024) void transpose_kernel(const float* __restrict__ x) {
    __shared__ float tile[64][33];               // [b_local][s_local]
    int s0 = blockIdx.x * 32;
    int b0 = blockIdx.y * 64;
    int tx = threadIdx.x;    // 0..31
    int ty = threadIdx.y;    // 0..31
    // coalesced reads along IN dimension (two 32-row passes)
    tile[ty][tx]      = x[(size_t)(b0 + ty)      * IN_FEAT + (s0 + tx)];
    tile[ty + 32][tx] = x[(size_t)(b0 + 32 + ty) * IN_FEAT + (s0 + tx)];
    __syncthreads();
    // warp ty owns xT row s0+ty; lane tx packs batch pair (2tx, 2tx+1)
    __half2 h = __floats2half2_rn(tile[2 * tx][ty], tile[2 * tx + 1][ty]);
    ((__half2*)g_xt)[(size_t)(s0 + ty) * (BATCH / 2) + (b0 / 2 + tx)] = h;
}

// ---------------- 2a) per-block histogram (smem only; coalesced global out) --
__global__ __launch_bounds__(1024) void hist_block_kernel(const int* __restrict__ dst,
                                                          int n, int chunk) {
    __shared__ int h[OUT_FEAT];
    for (int i = threadIdx.x; i < OUT_FEAT; i += 1024) h[i] = 0;
    __syncthreads();
    int b  = blockIdx.x;
    int lo = b * chunk;                      // chunk is a multiple of 4 -> aligned
    int hi = min(lo + chunk, n);
    int vend = lo + ((hi - lo) & ~3);
    for (int e = lo + threadIdx.x * 4; e + 3 < vend + 4 && e + 3 < hi + 4 && e < vend; e += 4096) {
        int4 d = *(const int4*)(dst + e);
        atomicAdd(&h[d.x], 1);
        atomicAdd(&h[d.y], 1);
        atomicAdd(&h[d.z], 1);
        atomicAdd(&h[d.w], 1);
    }
    for (int e = vend + threadIdx.x; e < hi; e += 1024)
        atomicAdd(&h[dst[e]], 1);
    __syncthreads();
    int* out = g_bh + b * OUT_FEAT;
    for (int i = threadIdx.x; i < OUT_FEAT; i += 1024) out[i] = h[i];
}

// ---------------- 2b) per-column scan over the NB block counts ---------------
__global__ __launch_bounds__(1024) void colscan_kernel() {
    __shared__ int tile[NB][33];
    int c0 = blockIdx.x * 32;
    int tx = threadIdx.x & 31;
    int ty = threadIdx.x >> 5;

#pragma unroll
    for (int p = 0; p < 8; p++) {
        int b = p * 32 + ty;
        int c = c0 + tx;
        tile[b][tx] = (c < OUT_FEAT) ? g_bh[b * OUT_FEAT + c] : 0;
    }
    __syncthreads();

    // warp ty owns tile column ty; lane tx owns rows [tx*8, tx*8+7]
    int vals[8];
    int lsum = 0;
#pragma unroll
    for (int k = 0; k < 8; k++) {
        vals[k] = tile[tx * 8 + k][ty];
        lsum += vals[k];
    }
    int s = lsum;
#pragma unroll
    for (int off = 1; off < 32; off <<= 1) {
        int u = __shfl_up_sync(0xFFFFFFFFu, s, off);
        if (tx >= off) s += u;
    }
    int run = s - lsum;
#pragma unroll
    for (int k = 0; k < 8; k++) {
        tile[tx * 8 + k][ty] = run;
        run += vals[k];
    }
    if (tx == 31 && (c0 + ty) < OUT_FEAT) g_cnt[c0 + ty] = run;  // column total
    __syncthreads();

#pragma unroll
    for (int p = 0; p < 8; p++) {
        int b = p * 32 + ty;
        int c = c0 + tx;
        if (c < OUT_FEAT) g_bh[b * OUT_FEAT + c] = tile[b][tx];
    }
}

// ---------------- 3) scatter; embeds the global column scan ------------------
#define SCAN_NPT 5   // 1024*5 = 5120 >= 5000
__global__ __launch_bounds__(1024) void scatter_block_kernel(const int* __restrict__ src,
                                                             const int* __restrict__ dst,
                                                             const float* __restrict__ w,
                                                             int n, int chunk) {
    __shared__ int cur[OUT_FEAT];
    __shared__ int wsum[32];
    int t = threadIdx.x;
    int lane = t & 31, wp = t >> 5;

    // ---- redundant exclusive scan of g_cnt into smem (removes scan kernel) --
    int local[SCAN_NPT];
    int sum = 0;
#pragma unroll
    for (int k = 0; k < SCAN_NPT; k++) {
        int idx = t * SCAN_NPT + k;
        int v = (idx < OUT_FEAT) ? g_cnt[idx] : 0;
        local[k] = v;
        sum += v;
    }
    int s = sum;
#pragma unroll
    for (int off = 1; off < 32; off <<= 1) {
        int u = __shfl_up_sync(0xFFFFFFFFu, s, off);
        if (lane >= off) s += u;
    }
    if (lane == 31) wsum[wp] = s;
    __syncthreads();
    if (wp == 0) {
        int sv = wsum[lane];
#pragma unroll
        for (int off = 1; off < 32; off <<= 1) {
            int u = __shfl_up_sync(0xFFFFFFFFu, sv, off);
            if (lane >= off) sv += u;
        }
        wsum[lane] = sv;
    }
    __syncthreads();
    int run = (wp > 0 ? wsum[wp - 1] : 0) + (s - sum);
#pragma unroll
    for (int k = 0; k < SCAN_NPT; k++) {
        int idx = t * SCAN_NPT + k;
        if (idx < OUT_FEAT) {
            cur[idx] = run;
            run += local[k];
        }
    }
    __syncthreads();

    // block 0 publishes g_start for spmm; then everyone adds its block offset.
    // (same thread touches the same i in both loops -> no extra sync needed)
    if (blockIdx.x == 0)
        for (int i = t; i < OUT_FEAT; i += 1024) g_start[i] = cur[i];
    const int* off = g_bh + blockIdx.x * OUT_FEAT;
    for (int i = t; i < OUT_FEAT; i += 1024) cur[i] += off[i];
    __syncthreads();

    // ---- scatter this block's edge chunk via smem cursors -------------------
    int lo = blockIdx.x * chunk;
    int hi = min(lo + chunk, n);
    for (int e = lo + t; e < hi; e += 1024) {
        int d = dst[e];
        int p = atomicAdd(&cur[d], 1);
        g_edge[p] = make_int2(src[e], __float_as_int(w[e]));
    }
}

// ---------------- 4) main SpMM: one column per CTA, 8 warps split edges ------
// Lane t holds batch elements [8t, 8t+7]. Inner loop accumulates 4 edges in
// fp16 (HFMA2) and drains into fp32 accumulators once per window.
__device__ __forceinline__ void accum8(float acc[8], uint4 v, float wv) {
    float2 f;
    f = __half22float2(*reinterpret_cast<__half2*>(&v.x)); acc[0] += wv * f.x; acc[1] += wv * f.y;
    f = __half22float2(*reinterpret_cast<__half2*>(&v.y)); acc[2] += wv * f.x; acc[3] += wv * f.y;
    f = __half22float2(*reinterpret_cast<__half2*>(&v.z)); acc[4] += wv * f.x; acc[5] += wv * f.y;
    f = __half22float2(*reinterpret_cast<__half2*>(&v.w)); acc[6] += wv * f.x; acc[7] += wv * f.y;
}

__global__ __launch_bounds__(256) void spmm_kernel(const float* __restrict__ bias,
                                                   float* __restrict__ out) {
    __shared__ float sAcc[8][BATCH];
    int warp = threadIdx.x >> 5;
    int t    = threadIdx.x & 31;
    const uint4* __restrict__ xt = (const uint4*)g_xt;   // 32 uint4 per xT row

    for (int col = blockIdx.x; col < OUT_FEAT; col += SPMM_CTAS) {
        int beg = g_start[col];
        int n   = g_cnt[col];
        int ch  = (n + 7) >> 3;
        int lo  = warp * ch;
        int hi  = min(lo + ch, n);
        const int2* __restrict__ ep = g_edge + beg;

        float acc[8] = {0.f, 0.f, 0.f, 0.f, 0.f, 0.f, 0.f, 0.f};

        int j = lo;
        for (; j + 4 <= hi; j += 4) {
            int2 e0 = __ldg(ep + j + 0);
            int2 e1 = __ldg(ep + j + 1);
            int2 e2 = __ldg(ep + j + 2);
            int2 e3 = __ldg(ep + j + 3);
            uint4 v0 = __ldg(xt + (size_t)e0.x * 32 + t);
            uint4 v1 = __ldg(xt + (size_t)e1.x * 32 + t);
            uint4 v2 = __ldg(xt + (size_t)e2.x * 32 + t);
            uint4 v3 = __ldg(xt + (size_t)e3.x * 32 + t);
            __half2 w0 = __float2half2_rn(__int_as_float(e0.y));
            __half2 w1 = __float2half2_rn(__int_as_float(e1.y));
            __half2 w2 = __float2half2_rn(__int_as_float(e2.y));
            __half2 w3 = __float2half2_rn(__int_as_float(e3.y));

            // fp16 window accumulators (4 edges deep)
            __half2 h0 = __hmul2(w0, *reinterpret_cast<__half2*>(&v0.x));
            __half2 h1 = __hmul2(w0, *reinterpret_cast<__half2*>(&v0.y));
            __half2 h2 = __hmul2(w0, *reinterpret_cast<__half2*>(&v0.z));
            __half2 h3 = __hmul2(w0, *reinterpret_cast<__half2*>(&v0.w));
            h0 = __hfma2(w1, *reinterpret_cast<__half2*>(&v1.x), h0);
            h1 = __hfma2(w1, *reinterpret_cast<__half2*>(&v1.y), h1);
            h2 = __hfma2(w1, *reinterpret_cast<__half2*>(&v1.z), h2);
            h3 = __hfma2(w1, *reinterpret_cast<__half2*>(&v1.w), h3);
            h0 = __hfma2(w2, *reinterpret_cast<__half2*>(&v2.x), h0);
            h1 = __hfma2(w2, *reinterpret_cast<__half2*>(&v2.y), h1);
            h2 = __hfma2(w2, *reinterpret_cast<__half2*>(&v2.z), h2);
            h3 = __hfma2(w2, *reinterpret_cast<__half2*>(&v2.w), h3);
            h0 = __hfma2(w3, *reinterpret_cast<__half2*>(&v3.x), h0);
            h1 = __hfma2(w3, *reinterpret_cast<__half2*>(&v3.y), h1);
            h2 = __hfma2(w3, *reinterpret_cast<__half2*>(&v3.z), h2);
            h3 = __hfma2(w3, *reinterpret_cast<__half2*>(&v3.w), h3);

            float2 f;
            f = __half22float2(h0); acc[0] += f.x; acc[1] += f.y;
            f = __half22float2(h1); acc[2] += f.x; acc[3] += f.y;
            f = __half22float2(h2); acc[4] += f.x; acc[5] += f.y;
            f = __half22float2(h3); acc[6] += f.x; acc[7] += f.y;
        }
        for (; j < hi; j++) {
            int2 e = __ldg(ep + j);
            uint4 v = __ldg(xt + (size_t)e.x * 32 + t);
            accum8(acc, v, __int_as_float(e.y));
        }

        float4* dstv = (float4*)&sAcc[warp][t * 8];
        dstv[0] = make_float4(acc[0], acc[1], acc[2], acc[3]);
        dstv[1] = make_float4(acc[4], acc[5], acc[6], acc[7]);
        __syncthreads();

        int b = threadIdx.x;
        float sred = sAcc[0][b] + sAcc[1][b] + sAcc[2][b] + sAcc[3][b]
                   + sAcc[4][b] + sAcc[5][b] + sAcc[6][b] + sAcc[7][b];
        float r = tanhf(sred + __ldg(bias + col));
        out[(size_t)b * OUT_FEAT + col] = r;
        __syncthreads();   // protect sAcc before next column overwrites it
    }
}

// ---------------- launch ------------------------------------------------------
extern "C" void kernel_launch(void* const* d_in, const int* in_sizes, int n_in,
                              void* d_out, int out_size) {
    const float* x    = (const float*)d_in[0];
    const int*   src  = (const int*)  d_in[1];
    const int*   dst  = (const int*)  d_in[2];
    const float* w    = (const float*)d_in[3];
    const float* bias = (const float*)d_in[4];
    float* out = (float*)d_out;

    int E = in_sizes[1];                          // NUM_EDGES
    int chunk = (((E + NB - 1) / NB) + 3) & ~3;   // multiple of 4 for int4 loads

    transpose_kernel<<<dim3(IN_FEAT / 32, BATCH / 64), dim3(32, 32)>>>(x);
    hist_block_kernel<<<NB, 1024>>>(dst, E, chunk);
    colscan_kernel<<<(OUT_FEAT + 31) / 32, 1024>>>();
    scatter_block_kernel<<<NB, 1024>>>(src, dst, w, E, chunk);
    spmm_kernel<<<SPMM_CTAS, 256>>>(bias, out);
}

// round 7
// speedup vs baseline: 2.3347x; 1.1683x over previous
#include <cuda_runtime.h>
#include <cuda_fp16.h>

// Problem constants (fixed for this dataset instance)
#define BATCH       256
#define IN_FEAT     20000
#define OUT_FEAT    5000
#define NUM_EDGES   1000000

#define NB          256          // counting-sort blocks
#define TR_BLOCKS   ((IN_FEAT / 32) * (BATCH / 64))   // 2500 transpose tiles
#define SPMM_CTAS   888          // 6 per SM on 148 SMs -> single wave, 48 warps/SM

// ---------------- scratch (no allocation allowed -> __device__ globals) ----
__device__ __half g_xt[IN_FEAT * BATCH];       // x transposed fp16: [IN_FEAT][BATCH], 10.24 MB
__device__ int2   g_edge[NUM_EDGES];           // dst-sorted edges: {src, w_as_int}, 8 MB
__device__ int    g_bh[NB * OUT_FEAT];         // per-block histograms / offsets, 5.12 MB
__device__ int    g_cnt[OUT_FEAT];             // edges per output column
__device__ int    g_start[OUT_FEAT];           // CSR row starts (written by scatter block 0)

// ---------------- 1) fused: transpose tiles + per-block histograms -----------
// Blocks [0, TR_BLOCKS): transpose a 64(b) x 32(s) tile of x into fp16 xT.
// Blocks [TR_BLOCKS, TR_BLOCKS+NB): smem histogram of a dst chunk -> g_bh.
__global__ __launch_bounds__(1024) void prep_kernel(const float* __restrict__ x,
                                                    const int* __restrict__ dst,
                                                    int n, int chunk) {
    __shared__ int smemU[OUT_FEAT];              // 20000 B; transpose uses 8448 B of it
    int t = threadIdx.x;

    if (blockIdx.x < TR_BLOCKS) {
        // ---------------- transpose tile ----------------
        float (*tile)[33] = (float (*)[33])smemU;   // [64][33]
        int tileIdx = blockIdx.x;
        int s0 = (tileIdx % (IN_FEAT / 32)) * 32;
        int b0 = (tileIdx / (IN_FEAT / 32)) * 64;
        int tx = t & 31;
        int ty = t >> 5;
        tile[ty][tx]      = x[(size_t)(b0 + ty)      * IN_FEAT + (s0 + tx)];
        tile[ty + 32][tx] = x[(size_t)(b0 + 32 + ty) * IN_FEAT + (s0 + tx)];
        __syncthreads();
        // warp ty owns xT row s0+ty; lane tx packs batch pair (2tx, 2tx+1)
        __half2 h = __floats2half2_rn(tile[2 * tx][ty], tile[2 * tx + 1][ty]);
        ((__half2*)g_xt)[(size_t)(s0 + ty) * (BATCH / 2) + (b0 / 2 + tx)] = h;
    } else {
        // ---------------- histogram block ----------------
        int* h = smemU;
        for (int i = t; i < OUT_FEAT; i += 1024) h[i] = 0;
        __syncthreads();
        int b  = blockIdx.x - TR_BLOCKS;
        int lo = b * chunk;                       // chunk multiple of 4 -> aligned
        int hi = min(lo + chunk, n);
        int cnt4 = (hi > lo) ? ((hi - lo) >> 2) : 0;
        const int4* d4 = (const int4*)(dst + lo);
        for (int i = t; i < cnt4; i += 1024) {
            int4 d = d4[i];
            atomicAdd(&h[d.x], 1);
            atomicAdd(&h[d.y], 1);
            atomicAdd(&h[d.z], 1);
            atomicAdd(&h[d.w], 1);
        }
        for (int e = lo + cnt4 * 4 + t; e < hi; e += 1024)
            atomicAdd(&h[dst[e]], 1);
        __syncthreads();
        int* out = g_bh + b * OUT_FEAT;
        for (int i = t; i < OUT_FEAT; i += 1024) out[i] = h[i];
    }
}

// ---------------- 2) per-column scan over the NB block counts ---------------
__global__ __launch_bounds__(1024) void colscan_kernel() {
    __shared__ int tile[NB][33];
    int c0 = blockIdx.x * 32;
    int tx = threadIdx.x & 31;
    int ty = threadIdx.x >> 5;

#pragma unroll
    for (int p = 0; p < 8; p++) {
        int b = p * 32 + ty;
        int c = c0 + tx;
        tile[b][tx] = (c < OUT_FEAT) ? g_bh[b * OUT_FEAT + c] : 0;
    }
    __syncthreads();

    // warp ty owns tile column ty; lane tx owns rows [tx*8, tx*8+7]
    int vals[8];
    int lsum = 0;
#pragma unroll
    for (int k = 0; k < 8; k++) {
        vals[k] = tile[tx * 8 + k][ty];
        lsum += vals[k];
    }
    int s = lsum;
#pragma unroll
    for (int off = 1; off < 32; off <<= 1) {
        int u = __shfl_up_sync(0xFFFFFFFFu, s, off);
        if (tx >= off) s += u;
    }
    int run = s - lsum;
#pragma unroll
    for (int k = 0; k < 8; k++) {
        tile[tx * 8 + k][ty] = run;
        run += vals[k];
    }
    if (tx == 31 && (c0 + ty) < OUT_FEAT) g_cnt[c0 + ty] = run;  // column total
    __syncthreads();

#pragma unroll
    for (int p = 0; p < 8; p++) {
        int b = p * 32 + ty;
        int c = c0 + tx;
        if (c < OUT_FEAT) g_bh[b * OUT_FEAT + c] = tile[b][tx];
    }
}

// ---------------- 3) scatter; embeds the global column scan ------------------
#define SCAN_NPT 5   // 1024*5 = 5120 >= 5000
__global__ __launch_bounds__(1024) void scatter_block_kernel(const int* __restrict__ src,
                                                             const int* __restrict__ dst,
                                                             const float* __restrict__ w,
                                                             int n, int chunk) {
    __shared__ int cur[OUT_FEAT];
    __shared__ int wsum[32];
    int t = threadIdx.x;
    int lane = t & 31, wp = t >> 5;

    // ---- redundant exclusive scan of g_cnt into smem ------------------------
    int local[SCAN_NPT];
    int sum = 0;
#pragma unroll
    for (int k = 0; k < SCAN_NPT; k++) {
        int idx = t * SCAN_NPT + k;
        int v = (idx < OUT_FEAT) ? g_cnt[idx] : 0;
        local[k] = v;
        sum += v;
    }
    int s = sum;
#pragma unroll
    for (int off = 1; off < 32; off <<= 1) {
        int u = __shfl_up_sync(0xFFFFFFFFu, s, off);
        if (lane >= off) s += u;
    }
    if (lane == 31) wsum[wp] = s;
    __syncthreads();
    if (wp == 0) {
        int sv = wsum[lane];
#pragma unroll
        for (int off = 1; off < 32; off <<= 1) {
            int u = __shfl_up_sync(0xFFFFFFFFu, sv, off);
            if (lane >= off) sv += u;
        }
        wsum[lane] = sv;
    }
    __syncthreads();
    int run = (wp > 0 ? wsum[wp - 1] : 0) + (s - sum);
#pragma unroll
    for (int k = 0; k < SCAN_NPT; k++) {
        int idx = t * SCAN_NPT + k;
        if (idx < OUT_FEAT) {
            cur[idx] = run;
            run += local[k];
        }
    }
    __syncthreads();

    // block 0 publishes g_start for spmm; then everyone adds its block offset.
    if (blockIdx.x == 0)
        for (int i = t; i < OUT_FEAT; i += 1024) g_start[i] = cur[i];
    const int* off = g_bh + blockIdx.x * OUT_FEAT;
    for (int i = t; i < OUT_FEAT; i += 1024) cur[i] += off[i];
    __syncthreads();

    // ---- scatter this block's chunk: int4 loads, 4 independent chains -------
    int lo = blockIdx.x * chunk;
    int hi = min(lo + chunk, n);
    if (hi > lo) {
        int cnt4 = (hi - lo) >> 2;
        const int4*   s4 = (const int4*)(src + lo);
        const int4*   d4 = (const int4*)(dst + lo);
        const float4* w4 = (const float4*)(w + lo);
        for (int i = t; i < cnt4; i += 1024) {
            int4   sv = s4[i];
            int4   dv = d4[i];
            float4 wv = w4[i];
            int p0 = atomicAdd(&cur[dv.x], 1);
            int p1 = atomicAdd(&cur[dv.y], 1);
            int p2 = atomicAdd(&cur[dv.z], 1);
            int p3 = atomicAdd(&cur[dv.w], 1);
            g_edge[p0] = make_int2(sv.x, __float_as_int(wv.x));
            g_edge[p1] = make_int2(sv.y, __float_as_int(wv.y));
            g_edge[p2] = make_int2(sv.z, __float_as_int(wv.z));
            g_edge[p3] = make_int2(sv.w, __float_as_int(wv.w));
        }
        for (int e = lo + cnt4 * 4 + t; e < hi; e += 1024) {
            int d = dst[e];
            int p = atomicAdd(&cur[d], 1);
            g_edge[p] = make_int2(src[e], __float_as_int(w[e]));
        }
    }
}

// ---------------- 4) main SpMM: one column per CTA, 8 warps split edges ------
// Lane t holds batch elements [8t, 8t+7]. Inner loop accumulates 4 edges in
// fp16 (HFMA2) and drains into fp32 accumulators once per window.
__device__ __forceinline__ void accum8(float acc[8], uint4 v, float wv) {
    float2 f;
    f = __half22float2(*reinterpret_cast<__half2*>(&v.x)); acc[0] += wv * f.x; acc[1] += wv * f.y;
    f = __half22float2(*reinterpret_cast<__half2*>(&v.y)); acc[2] += wv * f.x; acc[3] += wv * f.y;
    f = __half22float2(*reinterpret_cast<__half2*>(&v.z)); acc[4] += wv * f.x; acc[5] += wv * f.y;
    f = __half22float2(*reinterpret_cast<__half2*>(&v.w)); acc[6] += wv * f.x; acc[7] += wv * f.y;
}

__global__ __launch_bounds__(256, 6) void spmm_kernel(const float* __restrict__ bias,
                                                      float* __restrict__ out) {
    __shared__ float sAcc[8][BATCH];
    int warp = threadIdx.x >> 5;
    int t    = threadIdx.x & 31;
    const uint4* __restrict__ xt = (const uint4*)g_xt;   // 32 uint4 per xT row

    for (int col = blockIdx.x; col < OUT_FEAT; col += SPMM_CTAS) {
        int beg = g_start[col];
        int n   = g_cnt[col];
        int ch  = (n + 7) >> 3;
        int lo  = warp * ch;
        int hi  = min(lo + ch, n);
        const int2* __restrict__ ep = g_edge + beg;

        float acc[8] = {0.f, 0.f, 0.f, 0.f, 0.f, 0.f, 0.f, 0.f};

        int j = lo;
        for (; j + 4 <= hi; j += 4) {
            int2 e0 = __ldg(ep + j + 0);
            int2 e1 = __ldg(ep + j + 1);
            int2 e2 = __ldg(ep + j + 2);
            int2 e3 = __ldg(ep + j + 3);
            uint4 v0 = __ldg(xt + (size_t)e0.x * 32 + t);
            uint4 v1 = __ldg(xt + (size_t)e1.x * 32 + t);
            uint4 v2 = __ldg(xt + (size_t)e2.x * 32 + t);
            uint4 v3 = __ldg(xt + (size_t)e3.x * 32 + t);
            __half2 w0 = __float2half2_rn(__int_as_float(e0.y));
            __half2 w1 = __float2half2_rn(__int_as_float(e1.y));
            __half2 w2 = __float2half2_rn(__int_as_float(e2.y));
            __half2 w3 = __float2half2_rn(__int_as_float(e3.y));

            __half2 h0 = __hmul2(w0, *reinterpret_cast<__half2*>(&v0.x));
            __half2 h1 = __hmul2(w0, *reinterpret_cast<__half2*>(&v0.y));
            __half2 h2 = __hmul2(w0, *reinterpret_cast<__half2*>(&v0.z));
            __half2 h3 = __hmul2(w0, *reinterpret_cast<__half2*>(&v0.w));
            h0 = __hfma2(w1, *reinterpret_cast<__half2*>(&v1.x), h0);
            h1 = __hfma2(w1, *reinterpret_cast<__half2*>(&v1.y), h1);
            h2 = __hfma2(w1, *reinterpret_cast<__half2*>(&v1.z), h2);
            h3 = __hfma2(w1, *reinterpret_cast<__half2*>(&v1.w), h3);
            h0 = __hfma2(w2, *reinterpret_cast<__half2*>(&v2.x), h0);
            h1 = __hfma2(w2, *reinterpret_cast<__half2*>(&v2.y), h1);
            h2 = __hfma2(w2, *reinterpret_cast<__half2*>(&v2.z), h2);
            h3 = __hfma2(w2, *reinterpret_cast<__half2*>(&v2.w), h3);
            h0 = __hfma2(w3, *reinterpret_cast<__half2*>(&v3.x), h0);
            h1 = __hfma2(w3, *reinterpret_cast<__half2*>(&v3.y), h1);
            h2 = __hfma2(w3, *reinterpret_cast<__half2*>(&v3.z), h2);
            h3 = __hfma2(w3, *reinterpret_cast<__half2*>(&v3.w), h3);

            float2 f;
            f = __half22float2(h0); acc[0] += f.x; acc[1] += f.y;
            f = __half22float2(h1); acc[2] += f.x; acc[3] += f.y;
            f = __half22float2(h2); acc[4] += f.x; acc[5] += f.y;
            f = __half22float2(h3); acc[6] += f.x; acc[7] += f.y;
        }
        for (; j < hi; j++) {
            int2 e = __ldg(ep + j);
            uint4 v = __ldg(xt + (size_t)e.x * 32 + t);
            accum8(acc, v, __int_as_float(e.y));
        }

        float4* dstv = (float4*)&sAcc[warp][t * 8];
        dstv[0] = make_float4(acc[0], acc[1], acc[2], acc[3]);
        dstv[1] = make_float4(acc[4], acc[5], acc[6], acc[7]);
        __syncthreads();

        int b = threadIdx.x;
        float sred = sAcc[0][b] + sAcc[1][b] + sAcc[2][b] + sAcc[3][b]
                   + sAcc[4][b] + sAcc[5][b] + sAcc[6][b] + sAcc[7][b];
        float r = tanhf(sred + __ldg(bias + col));
        out[(size_t)b * OUT_FEAT + col] = r;
        __syncthreads();   // protect sAcc before next column overwrites it
    }
}

// ---------------- launch ------------------------------------------------------
extern "C" void kernel_launch(void* const* d_in, const int* in_sizes, int n_in,
                              void* d_out, int out_size) {
    const float* x    = (const float*)d_in[0];
    const int*   src  = (const int*)  d_in[1];
    const int*   dst  = (const int*)  d_in[2];
    const float* w    = (const float*)d_in[3];
    const float* bias = (const float*)d_in[4];
    float* out = (float*)d_out;

    int E = in_sizes[1];                          // NUM_EDGES
    int chunk = (((E + NB - 1) / NB) + 3) & ~3;   // multiple of 4 for int4 loads

    prep_kernel<<<TR_BLOCKS + NB, 1024>>>(x, dst, E, chunk);
    colscan_kernel<<<(OUT_FEAT + 31) / 32, 1024>>>();
    scatter_block_kernel<<<NB, 1024>>>(src, dst, w, E, chunk);
    spmm_kernel<<<SPMM_CTAS, 256>>>(bias, out);
}